// round 11
// baseline (speedup 1.0000x reference)
#include <cuda_runtime.h>
#include <math.h>

// ---------------- static scratch (no runtime allocation allowed) ----------------
#define TBL_N    1024
#define TBL_MAX  8.0f
#define NMAX     65536
#define EMAX     1700000

__device__ float4 g_table[TBL_N];            // (alpha,gamma,delta,beta') gate coeffs
__device__ float4 g_node[NMAX * 4];          // per node (64B): {pos,_},{Ai0-3},{Ai4-7},pad
__device__ int    g_cnt[NMAX];               // edge counts per dst (self-cleaning)
__device__ int    g_off[NMAX + 1];           // CSR offsets
__device__ unsigned long long g_aggflag[256];// lookback scan: (flag<<32)|aggregate
__device__ int    g_cellflag;                // 1 if cell has any nonzero entry
__device__ int    g_rank[EMAX];              // per-edge rank within dst segment
__device__ int    g_csr[EMAX];               // CSR: src node id per slot
__device__ int    g_eid[EMAX];               // CSR: edge id per slot (only if cellflag)

__device__ __forceinline__ float siluf(float x) { return x / (1.0f + expf(-x)); }

// ---------------- K1: fused prep (gate table | node pack+MLP | count+rank) ----------------
__global__ void __launch_bounds__(256) prep_kernel(
                            const float* __restrict__ f1, const float* __restrict__ fb1,
                            const float* __restrict__ f2, const float* __restrict__ fb2,
                            const float* __restrict__ f3, const float* __restrict__ fb3,
                            const float* __restrict__ emb_table, const int* __restrict__ A,
                            const float* __restrict__ w1, const float* __restrict__ b1,
                            const float* __restrict__ w2, const float* __restrict__ b2,
                            const float* __restrict__ pos, const float* __restrict__ cell,
                            const int* __restrict__ edst,
                            int N, int E)
{
    int tid = threadIdx.x;
    int bx = blockIdx.x;
    int nbTbl  = TBL_N / 256;
    int nbNode = (N + 255) / 256;

    if (bx < nbTbl) {
        // ---- gate table role (h1 fully register-resident: all indices static) ----
        if (bx == 0 && tid == 0) {
            int fl = 0;
            for (int i = 0; i < 9; i++) fl |= (cell[i] != 0.0f);
            g_cellflag = fl;
        }
        __shared__ float sf1[16 * 64];
        __shared__ float sf2[64 * 64];
        __shared__ float sf3[64 * 5];
        __shared__ float sb1[64], sb2[64], sb3[5];
        for (int i = tid; i < 16 * 64; i += 256) sf1[i] = f1[i];
        for (int i = tid; i < 64 * 64; i += 256) sf2[i] = f2[i];
        for (int i = tid; i < 64 * 5;  i += 256) sf3[i] = f3[i];
        if (tid < 64) { sb1[tid] = fb1[tid]; sb2[tid] = fb2[tid]; }
        if (tid < 5)  sb3[tid] = fb3[tid];
        __syncthreads();

        int idx = bx * 256 + tid;
        float x = (float)idx * (TBL_MAX / (float)TBL_N);
        float emb[16];
#pragma unroll
        for (int k = 0; k < 16; k++) {
            float c = (5.0f / 17.0f) * (float)(k + 1);
            float z = (x - c) * (17.0f / 5.0f);
            emb[k] = 3.57142857142857f * expf(-z * z);
        }
        float h1[64];
#pragma unroll
        for (int j = 0; j < 64; j++) {        // FULL unroll -> h1 writes static
            float a = sb1[j];
#pragma unroll
            for (int k = 0; k < 16; k++) a = fmaf(emb[k], sf1[k * 64 + j], a);
            h1[j] = siluf(a);
        }
        float g0 = sb3[0], g1 = sb3[1], g2 = sb3[2], g3 = sb3[3];
        for (int j = 0; j < 64; j++) {        // dynamic outer is fine
            float a = sb2[j];
#pragma unroll
            for (int k = 0; k < 64; k++)      // FULL unroll -> h1 reads static
                a = fmaf(h1[k], sf2[k * 64 + j], a);
            float h = siluf(a);
            g0 = fmaf(h, sf3[j * 5 + 0], g0);
            g1 = fmaf(h, sf3[j * 5 + 1], g1);
            g2 = fmaf(h, sf3[j * 5 + 2], g2);
            g3 = fmaf(h, sf3[j * 5 + 3], g3);
            // path (1,1,1): eps_mno n_m n_n == 0 -> dead, g4 never needed
        }
        const float IS8 = 0.3535533905932738f;
        const float IS3 = 0.5773502691896258f;
        float4 T;
        T.x = g0 * IS8;          // alpha
        T.y = g1 * IS8;          // gamma
        T.z = g2 * IS8;          // delta
        T.w = g3 * IS8 * IS3;    // beta (pre s2)
        g_table[idx] = T;
    } else if (bx < nbTbl + nbNode) {
        // ---- node MLP + pack role ----
        __shared__ float sw1[16 * 64];
        __shared__ float sw2[64 * 8];
        __shared__ float nb1[64], nb2[8];
        for (int i = tid; i < 16 * 64; i += 256) sw1[i] = w1[i];
        for (int i = tid; i < 64 * 8;  i += 256) sw2[i] = w2[i];
        if (tid < 64) nb1[tid] = b1[tid];
        if (tid < 8)  nb2[tid] = b2[tid];
        __syncthreads();

        int n = (bx - nbTbl) * 256 + tid;
        if (n >= N) return;
        int a = A[n];
        const float4* ep = (const float4*)(emb_table + (size_t)a * 16);
        float4 e0 = __ldg(ep + 0), e1 = __ldg(ep + 1), e2 = __ldg(ep + 2), e3 = __ldg(ep + 3);
        float e[16] = { e0.x, e0.y, e0.z, e0.w, e1.x, e1.y, e1.z, e1.w,
                        e2.x, e2.y, e2.z, e2.w, e3.x, e3.y, e3.z, e3.w };
        float acc[8];
#pragma unroll
        for (int u = 0; u < 8; u++) acc[u] = nb2[u];
        for (int j = 0; j < 64; j++) {
            float h = nb1[j];
#pragma unroll
            for (int k = 0; k < 16; k++) h = fmaf(e[k], sw1[k * 64 + j], h);
            h = siluf(h);
#pragma unroll
            for (int u = 0; u < 8; u++) acc[u] = fmaf(h, sw2[j * 8 + u], acc[u]);
        }
        g_node[4 * n + 0] = make_float4(pos[3 * n], pos[3 * n + 1], pos[3 * n + 2], 0.f);
        g_node[4 * n + 1] = make_float4(acc[0], acc[1], acc[2], acc[3]);
        g_node[4 * n + 2] = make_float4(acc[4], acc[5], acc[6], acc[7]);
    } else {
        // ---- count + rank role (independent of the other roles) ----
        int cb = bx - nbTbl - nbNode;
        if (cb == 0 && tid < 256) g_aggflag[tid] = 0ULL;
        int i = (cb * 256 + tid) * 4;
        if (i + 3 < E) {
            int4 d = *(const int4*)(edst + i);
            int4 r;
            r.x = atomicAdd(&g_cnt[d.x], 1);
            r.y = atomicAdd(&g_cnt[d.y], 1);
            r.z = atomicAdd(&g_cnt[d.z], 1);
            r.w = atomicAdd(&g_cnt[d.w], 1);
            *(int4*)(g_rank + i) = r;
        } else {
            for (int k = i; k < E; k++) g_rank[k] = atomicAdd(&g_cnt[edst[k]], 1);
        }
    }
}

// ---------------- K2: single-pass lookback scan -> offsets; self-clean counts ----------------
__global__ void scan_kernel(int N, int E)
{
    __shared__ int sm[256];
    __shared__ int sr[256];
    int t = threadIdx.x;
    int bx = blockIdx.x;
    int i = bx * 256 + t;
    int v = (i < N) ? g_cnt[i] : 0;
    if (i < N) g_cnt[i] = 0;          // reset for next graph replay

    sm[t] = v;
    __syncthreads();
#pragma unroll
    for (int d = 1; d < 256; d <<= 1) {
        int x = (t >= d) ? sm[t - d] : 0;
        __syncthreads();
        sm[t] += x;
        __syncthreads();
    }
    // publish aggregate (flag in high word, value in low word -> single 8B word, no fence)
    if (t == 0) atomicExch(&g_aggflag[bx], (1ULL << 32) | (unsigned int)sm[255]);

    // parallel lookback: thread t (< bx) polls block t's aggregate (plain volatile 8B load)
    int pre = 0;
    if (t < bx) {
        const volatile unsigned long long* p = (const volatile unsigned long long*)&g_aggflag[t];
        unsigned long long x;
        do { x = *p; } while (!(x >> 32));
        pre = (int)(unsigned int)x;
    }
    sr[t] = pre;
    __syncthreads();
#pragma unroll
    for (int d = 128; d > 0; d >>= 1) {
        if (t < d) sr[t] += sr[t + d];
        __syncthreads();
    }
    int prefix = sr[0];

    if (i < N) g_off[i] = prefix + sm[t] - v;   // exclusive
    if (bx == 0 && t == 0) g_off[N] = E;
}

// ---------------- K3: permute edges into CSR -- NO atomics (off + rank) ----------------
__global__ void permute_kernel(const int* __restrict__ esrc, const int* __restrict__ edst, int E)
{
    int cf = g_cellflag;
    int i = (blockIdx.x * blockDim.x + threadIdx.x) * 4;
    if (i + 3 < E) {
        int4 s4 = *(const int4*)(esrc + i);
        int4 d4 = *(const int4*)(edst + i);
        int4 r4 = *(const int4*)(g_rank + i);
        int sl;
        sl = __ldg(&g_off[d4.x]) + r4.x; g_csr[sl] = s4.x; if (cf) g_eid[sl] = i;
        sl = __ldg(&g_off[d4.y]) + r4.y; g_csr[sl] = s4.y; if (cf) g_eid[sl] = i + 1;
        sl = __ldg(&g_off[d4.z]) + r4.z; g_csr[sl] = s4.z; if (cf) g_eid[sl] = i + 2;
        sl = __ldg(&g_off[d4.w]) + r4.w; g_csr[sl] = s4.w; if (cf) g_eid[sl] = i + 3;
    } else {
        for (int k = i; k < E; k++) {
            int sl = __ldg(&g_off[edst[k]]) + g_rank[k];
            g_csr[sl] = esrc[k];
            if (cf) g_eid[sl] = k;
        }
    }
}

// ---------------- K4: gather: 64 nodes/block, smem table, warp-per-node ----------------
__global__ void __launch_bounds__(256, 5) gather_kernel(
    const float* __restrict__ shifts, const float* __restrict__ cell,
    const float* __restrict__ tpw, float* __restrict__ out, int N, float scale)
{
    __shared__ float4 sTab[TBL_N];      // 16KB gate table (block-resident)
    __shared__ float  sT[8][16][34];    // per-warp transposed staging
    __shared__ float  sAcc[8][64];      // per-node sufficient statistics
    __shared__ float  sW[1024];         // tpw[4 paths][8][32]

    int tid = threadIdx.x;
    int w   = tid >> 5;                 // warp slot
    int l   = tid & 31;                 // lane
    for (int i = tid; i < 1024; i += 256) sW[i] = __ldg(tpw + i);
    for (int i = tid; i < TBL_N; i += 256) sTab[i] = g_table[i];
    __syncthreads();

    int cf = g_cellflag;
    int j0 = l >> 3;                    // s row (0..3); second acc uses j0+4
    int u  = l & 7;                     // Ai column
    float (*T)[34] = sT[w];

    // finalize weights (loop-invariant)
    int col = tid & 127;
    float wa[8], wb[8];
    int ra, rb;
    if (col < 32) {
        int v = col;
#pragma unroll
        for (int uu = 0; uu < 8; uu++) {
            wa[uu] = sW[0 * 256 + uu * 32 + v];   // W0 * alpha row
            wb[uu] = sW[3 * 256 + uu * 32 + v];   // W3 * beta row
        }
        ra = 0; rb = 8;
    } else {
        int q = col - 32;
        int v = q / 3, o = q - 3 * v;
#pragma unroll
        for (int uu = 0; uu < 8; uu++) {
            wa[uu] = sW[1 * 256 + uu * 32 + v];   // W1 * gamma*n_o rows
            wb[uu] = sW[2 * 256 + uu * 32 + v];   // W2 * delta*n_o rows
        }
        ra = (2 + o) * 8; rb = (5 + o) * 8;
    }
    int w0 = tid >> 7;                  // 0 or 1 for finalize split

    for (int b = 0; b < 8; b++) {       // 8 batches of 8 nodes
        int node = blockIdx.x * 64 + b * 8 + w;
        int base = 0, end = 0;
        if (node < N) { base = g_off[node]; end = g_off[node + 1]; }
        int deg = end - base;
        int nch = (deg + 31) >> 5;

        float4 pd = make_float4(0.f, 0.f, 0.f, 0.f);
        if (node < N) pd = __ldg(&g_node[4 * node]);   // warp-uniform broadcast

        float acc0 = 0.0f, acc1 = 0.0f;

        for (int ch = 0; ch < nch; ch++) {
            int i = base + ch * 32 + l;
            if (i < end) {
                int src = __ldg(&g_csr[i]);
                float4 ps = __ldg(&g_node[4 * src]);
                float4 A0 = __ldg(&g_node[4 * src + 1]);
                float4 A1 = __ldg(&g_node[4 * src + 2]);
                float vx = pd.x - ps.x;
                float vy = pd.y - ps.y;
                float vz = pd.z - ps.z;
                if (cf) {   // exact: when cell==0 the shift term is identically 0
                    int e = __ldg(&g_eid[i]);
                    float shx = __ldg(shifts + 3 * e + 0);
                    float shy = __ldg(shifts + 3 * e + 1);
                    float shz = __ldg(shifts + 3 * e + 2);
                    vx += shx * __ldg(cell + 0) + shy * __ldg(cell + 3) + shz * __ldg(cell + 6);
                    vy += shx * __ldg(cell + 1) + shy * __ldg(cell + 4) + shz * __ldg(cell + 7);
                    vz += shx * __ldg(cell + 2) + shy * __ldg(cell + 5) + shz * __ldg(cell + 8);
                }
                float len = sqrtf(vx * vx + vy * vy + vz * vz);
                float inv = 1.0f / fmaxf(len, 1e-8f);
                float nx = vx * inv, ny = vy * inv, nz = vz * inv;
                float s2 = nx * nx + ny * ny + nz * nz;   // 1 except degenerate edges

                float t = fminf(len * ((float)TBL_N / TBL_MAX), (float)TBL_N - 1.001f);
                int   i0 = (int)t;
                float fr = t - (float)i0;
                float4 Ta = sTab[i0];
                float4 Tb = sTab[i0 + 1];
                float alpha = fmaf(fr, Tb.x - Ta.x, Ta.x);
                float gamma = fmaf(fr, Tb.y - Ta.y, Ta.y);
                float delta = fmaf(fr, Tb.z - Ta.z, Ta.z);
                float beta  = fmaf(fr, Tb.w - Ta.w, Ta.w) * s2;

                // transposed store: 16 conflict-free scalar STS (bank = (2k+l) mod 32)
                T[0][l]  = alpha;       T[1][l]  = beta;
                T[2][l]  = gamma * nx;  T[3][l]  = gamma * ny;
                T[4][l]  = gamma * nz;  T[5][l]  = delta * nx;
                T[6][l]  = delta * ny;  T[7][l]  = delta * nz;
                T[8][l]  = A0.x;  T[9][l]  = A0.y;  T[10][l] = A0.z;  T[11][l] = A0.w;
                T[12][l] = A1.x;  T[13][l] = A1.y;  T[14][l] = A1.z;  T[15][l] = A1.w;
            }
            __syncwarp();
            int m = deg - ch * 32;
            if (m > 32) m = 32;
            if (m == 32) {
#pragma unroll
                for (int c = 0; c < 32; c += 2) {       // LDS.64: 2 edges per iteration
                    float2 a  = *(const float2*)&T[8 + u][c];
                    float2 s0 = *(const float2*)&T[j0][c];
                    float2 s1 = *(const float2*)&T[j0 + 4][c];
                    acc0 = fmaf(s0.x, a.x, acc0);
                    acc0 = fmaf(s0.y, a.y, acc0);
                    acc1 = fmaf(s1.x, a.x, acc1);
                    acc1 = fmaf(s1.y, a.y, acc1);
                }
            } else {
                int mp = m & ~1;
                for (int c = 0; c < mp; c += 2) {
                    float2 a  = *(const float2*)&T[8 + u][c];
                    float2 s0 = *(const float2*)&T[j0][c];
                    float2 s1 = *(const float2*)&T[j0 + 4][c];
                    acc0 = fmaf(s0.x, a.x, acc0);
                    acc0 = fmaf(s0.y, a.y, acc0);
                    acc1 = fmaf(s1.x, a.x, acc1);
                    acc1 = fmaf(s1.y, a.y, acc1);
                }
                if (m & 1) {
                    float a = T[8 + u][mp];
                    acc0 = fmaf(T[j0][mp],     a, acc0);
                    acc1 = fmaf(T[j0 + 4][mp], a, acc1);
                }
            }
            __syncwarp();
        }
        sAcc[w][l]      = acc0;           // entry (j0,  u)
        sAcc[w][l + 32] = acc1;           // entry (j0+4,u)
        __syncthreads();

        // ---- finalize this batch: 8 nodes x 128 cols ----
#pragma unroll
        for (int k = 0; k < 4; k++) {
            int ws = w0 + k * 2;
            int nd = blockIdx.x * 64 + b * 8 + ws;
            if (nd >= N) break;
            float sum = 0.0f;
#pragma unroll
            for (int uu = 0; uu < 8; uu++) {
                sum = fmaf(wa[uu], sAcc[ws][ra + uu], sum);
                sum = fmaf(wb[uu], sAcc[ws][rb + uu], sum);
            }
            out[(size_t)nd * 128 + col] = sum * scale;
        }
        __syncthreads();
    }
}

// ---------------- launch ----------------
extern "C" void kernel_launch(void* const* d_in, const int* in_sizes, int n_in,
                              void* d_out, int out_size)
{
    const float* pos       = (const float*)d_in[0];
    const int*   A         = (const int*)  d_in[1];
    const int*   esrc      = (const int*)  d_in[3];
    const int*   edst      = (const int*)  d_in[4];
    const float* shifts    = (const float*)d_in[5];
    const float* cell      = (const float*)d_in[6];
    const float* emb_table = (const float*)d_in[7];
    const float* w1  = (const float*)d_in[8];
    const float* b1  = (const float*)d_in[9];
    const float* w2  = (const float*)d_in[10];
    const float* b2  = (const float*)d_in[11];
    const float* f1  = (const float*)d_in[12];
    const float* fb1 = (const float*)d_in[13];
    const float* f2  = (const float*)d_in[14];
    const float* fb2 = (const float*)d_in[15];
    const float* f3  = (const float*)d_in[16];
    const float* fb3 = (const float*)d_in[17];
    const float* tpw = (const float*)d_in[18];

    int N = in_sizes[1];
    int E = in_sizes[3];

    int nbTbl   = TBL_N / 256;
    int nbNode  = (N + 255) / 256;
    int nbCount = (E + 1023) / 1024;
    int nbScan  = (N + 255) / 256;

    prep_kernel<<<nbTbl + nbNode + nbCount, 256>>>(f1, fb1, f2, fb2, f3, fb3,
                                                   emb_table, A, w1, b1, w2, b2,
                                                   pos, cell, edst, N, E);
    scan_kernel<<<nbScan, 256>>>(N, E);
    permute_kernel<<<(E + 1023) / 1024, 256>>>(esrc, edst, E);
    gather_kernel<<<(N + 63) / 64, 256>>>(shifts, cell, tpw, (float*)d_out, N, (float)N / (float)E);
}

// round 13
// speedup vs baseline: 1.1155x; 1.1155x over previous
#include <cuda_runtime.h>
#include <math.h>

// ---------------- static scratch (no runtime allocation allowed) ----------------
#define TBL_N    1024
#define TBL_MAX  8.0f
#define NMAX     65536
#define EMAX     1700000

__device__ float4 g_table[TBL_N];            // (alpha,gamma,delta,beta') gate coeffs
__device__ float4 g_node[NMAX * 4];          // per node (64B): {pos,_},{Ai0-3},{Ai4-7},pad
__device__ int    g_cnt[NMAX];               // edge counts per dst (self-cleaning)
__device__ int    g_off[NMAX + 1];           // CSR offsets
__device__ unsigned long long g_aggflag[256];// lookback scan: (flag<<32)|aggregate
__device__ int    g_cellflag;                // 1 if cell has any nonzero entry
__device__ int    g_rank[EMAX];              // per-edge rank within dst segment
__device__ int    g_csr[EMAX];               // CSR: src node id per slot
__device__ int    g_eid[EMAX];               // CSR: edge id per slot (only if cellflag)

__device__ __forceinline__ float siluf(float x) { return x / (1.0f + expf(-x)); }

// ---------------- K1: fused prep (gate table | node pack+MLP | count+rank) ----------------
__global__ void __launch_bounds__(256) prep_kernel(
                            const float* __restrict__ f1, const float* __restrict__ fb1,
                            const float* __restrict__ f2, const float* __restrict__ fb2,
                            const float* __restrict__ f3, const float* __restrict__ fb3,
                            const float* __restrict__ emb_table, const int* __restrict__ A,
                            const float* __restrict__ w1, const float* __restrict__ b1,
                            const float* __restrict__ w2, const float* __restrict__ b2,
                            const float* __restrict__ pos, const float* __restrict__ cell,
                            const int* __restrict__ edst,
                            int N, int E)
{
    int tid = threadIdx.x;
    int bx = blockIdx.x;
    int nbTbl  = TBL_N / 256;
    int nbNode = (N + 255) / 256;

    if (bx < nbTbl) {
        // ---- gate table role (h1 fully register-resident: all indices static) ----
        if (bx == 0 && tid == 0) {
            int fl = 0;
            for (int i = 0; i < 9; i++) fl |= (cell[i] != 0.0f);
            g_cellflag = fl;
        }
        __shared__ float sf1[16 * 64];
        __shared__ float sf2[64 * 64];
        __shared__ float sf3[64 * 5];
        __shared__ float sb1[64], sb2[64], sb3[5];
        for (int i = tid; i < 16 * 64; i += 256) sf1[i] = f1[i];
        for (int i = tid; i < 64 * 64; i += 256) sf2[i] = f2[i];
        for (int i = tid; i < 64 * 5;  i += 256) sf3[i] = f3[i];
        if (tid < 64) { sb1[tid] = fb1[tid]; sb2[tid] = fb2[tid]; }
        if (tid < 5)  sb3[tid] = fb3[tid];
        __syncthreads();

        int idx = bx * 256 + tid;
        float x = (float)idx * (TBL_MAX / (float)TBL_N);
        float emb[16];
#pragma unroll
        for (int k = 0; k < 16; k++) {
            float c = (5.0f / 17.0f) * (float)(k + 1);
            float z = (x - c) * (17.0f / 5.0f);
            emb[k] = 3.57142857142857f * expf(-z * z);
        }
        float h1[64];
#pragma unroll
        for (int j = 0; j < 64; j++) {        // FULL unroll -> h1 writes static
            float a = sb1[j];
#pragma unroll
            for (int k = 0; k < 16; k++) a = fmaf(emb[k], sf1[k * 64 + j], a);
            h1[j] = siluf(a);
        }
        float g0 = sb3[0], g1 = sb3[1], g2 = sb3[2], g3 = sb3[3];
        for (int j = 0; j < 64; j++) {        // dynamic outer is fine
            float a = sb2[j];
#pragma unroll
            for (int k = 0; k < 64; k++)      // FULL unroll -> h1 reads static
                a = fmaf(h1[k], sf2[k * 64 + j], a);
            float h = siluf(a);
            g0 = fmaf(h, sf3[j * 5 + 0], g0);
            g1 = fmaf(h, sf3[j * 5 + 1], g1);
            g2 = fmaf(h, sf3[j * 5 + 2], g2);
            g3 = fmaf(h, sf3[j * 5 + 3], g3);
            // path (1,1,1): eps_mno n_m n_n == 0 -> dead, g4 never needed
        }
        const float IS8 = 0.3535533905932738f;
        const float IS3 = 0.5773502691896258f;
        float4 T;
        T.x = g0 * IS8;          // alpha
        T.y = g1 * IS8;          // gamma
        T.z = g2 * IS8;          // delta
        T.w = g3 * IS8 * IS3;    // beta (pre s2)
        g_table[idx] = T;
    } else if (bx < nbTbl + nbNode) {
        // ---- node MLP + pack role ----
        __shared__ float sw1[16 * 64];
        __shared__ float sw2[64 * 8];
        __shared__ float nb1[64], nb2[8];
        for (int i = tid; i < 16 * 64; i += 256) sw1[i] = w1[i];
        for (int i = tid; i < 64 * 8;  i += 256) sw2[i] = w2[i];
        if (tid < 64) nb1[tid] = b1[tid];
        if (tid < 8)  nb2[tid] = b2[tid];
        __syncthreads();

        int n = (bx - nbTbl) * 256 + tid;
        if (n >= N) return;
        int a = A[n];
        const float4* ep = (const float4*)(emb_table + (size_t)a * 16);
        float4 e0 = __ldg(ep + 0), e1 = __ldg(ep + 1), e2 = __ldg(ep + 2), e3 = __ldg(ep + 3);
        float e[16] = { e0.x, e0.y, e0.z, e0.w, e1.x, e1.y, e1.z, e1.w,
                        e2.x, e2.y, e2.z, e2.w, e3.x, e3.y, e3.z, e3.w };
        float acc[8];
#pragma unroll
        for (int u = 0; u < 8; u++) acc[u] = nb2[u];
        for (int j = 0; j < 64; j++) {
            float h = nb1[j];
#pragma unroll
            for (int k = 0; k < 16; k++) h = fmaf(e[k], sw1[k * 64 + j], h);
            h = siluf(h);
#pragma unroll
            for (int u = 0; u < 8; u++) acc[u] = fmaf(h, sw2[j * 8 + u], acc[u]);
        }
        g_node[4 * n + 0] = make_float4(pos[3 * n], pos[3 * n + 1], pos[3 * n + 2], 0.f);
        g_node[4 * n + 1] = make_float4(acc[0], acc[1], acc[2], acc[3]);
        g_node[4 * n + 2] = make_float4(acc[4], acc[5], acc[6], acc[7]);
    } else {
        // ---- count + rank role (independent of the other roles) ----
        int cb = bx - nbTbl - nbNode;
        if (cb == 0 && tid < 256) g_aggflag[tid] = 0ULL;
        int i = (cb * 256 + tid) * 4;
        if (i + 3 < E) {
            int4 d = *(const int4*)(edst + i);
            int4 r;
            r.x = atomicAdd(&g_cnt[d.x], 1);
            r.y = atomicAdd(&g_cnt[d.y], 1);
            r.z = atomicAdd(&g_cnt[d.z], 1);
            r.w = atomicAdd(&g_cnt[d.w], 1);
            *(int4*)(g_rank + i) = r;
        } else {
            for (int k = i; k < E; k++) g_rank[k] = atomicAdd(&g_cnt[edst[k]], 1);
        }
    }
}

// ---------------- K2: single-pass lookback scan -> offsets; self-clean counts ----------------
__global__ void scan_kernel(int N, int E)
{
    __shared__ int sm[256];
    __shared__ int sr[256];
    int t = threadIdx.x;
    int bx = blockIdx.x;
    int i = bx * 256 + t;
    int v = (i < N) ? g_cnt[i] : 0;
    if (i < N) g_cnt[i] = 0;          // reset for next graph replay

    sm[t] = v;
    __syncthreads();
#pragma unroll
    for (int d = 1; d < 256; d <<= 1) {
        int x = (t >= d) ? sm[t - d] : 0;
        __syncthreads();
        sm[t] += x;
        __syncthreads();
    }
    // publish aggregate (flag in high word, value in low word -> single 8B word, no fence)
    if (t == 0) atomicExch(&g_aggflag[bx], (1ULL << 32) | (unsigned int)sm[255]);

    // parallel lookback: thread t (< bx) polls block t's aggregate (plain volatile 8B load)
    int pre = 0;
    if (t < bx) {
        const volatile unsigned long long* p = (const volatile unsigned long long*)&g_aggflag[t];
        unsigned long long x;
        do { x = *p; } while (!(x >> 32));
        pre = (int)(unsigned int)x;
    }
    sr[t] = pre;
    __syncthreads();
#pragma unroll
    for (int d = 128; d > 0; d >>= 1) {
        if (t < d) sr[t] += sr[t + d];
        __syncthreads();
    }
    int prefix = sr[0];

    if (i < N) g_off[i] = prefix + sm[t] - v;   // exclusive
    if (bx == 0 && t == 0) g_off[N] = E;
}

// ---------------- K3: permute edges into CSR -- NO atomics (off + rank) ----------------
__global__ void permute_kernel(const int* __restrict__ esrc, const int* __restrict__ edst, int E)
{
    int cf = g_cellflag;
    int i = (blockIdx.x * blockDim.x + threadIdx.x) * 4;
    if (i + 3 < E) {
        int4 s4 = *(const int4*)(esrc + i);
        int4 d4 = *(const int4*)(edst + i);
        int4 r4 = *(const int4*)(g_rank + i);
        int sl;
        sl = __ldg(&g_off[d4.x]) + r4.x; g_csr[sl] = s4.x; if (cf) g_eid[sl] = i;
        sl = __ldg(&g_off[d4.y]) + r4.y; g_csr[sl] = s4.y; if (cf) g_eid[sl] = i + 1;
        sl = __ldg(&g_off[d4.z]) + r4.z; g_csr[sl] = s4.z; if (cf) g_eid[sl] = i + 2;
        sl = __ldg(&g_off[d4.w]) + r4.w; g_csr[sl] = s4.w; if (cf) g_eid[sl] = i + 3;
    } else {
        for (int k = i; k < E; k++) {
            int sl = __ldg(&g_off[edst[k]]) + g_rank[k];
            g_csr[sl] = esrc[k];
            if (cf) g_eid[sl] = k;
        }
    }
}

// ---------------- K4: warp-per-node gather (R9 structure) + fused finalize ----------------
__global__ void __launch_bounds__(256) gather_kernel(
    const float* __restrict__ shifts, const float* __restrict__ cell,
    const float* __restrict__ tpw, float* __restrict__ out, int N, float scale)
{
    __shared__ float sT[8][16][34];     // per-warp transposed staging (stride 34)
    __shared__ float sAcc[8][64];       // per-node sufficient statistics
    __shared__ float sW[1024];          // tpw[4 paths][8][32]

    int tid = threadIdx.x;
    int w   = tid >> 5;                 // warp / node slot
    int l   = tid & 31;                 // lane
    for (int i = tid; i < 1024; i += 256) sW[i] = __ldg(tpw + i);

    int node = blockIdx.x * 8 + w;
    int base = 0, end = 0;
    if (node < N) { base = g_off[node]; end = g_off[node + 1]; }
    int deg = end - base;
    int nch = (deg + 31) >> 5;
    int cf  = g_cellflag;

    float4 pd = make_float4(0.f, 0.f, 0.f, 0.f);
    if (node < N) pd = __ldg(&g_node[4 * node]);   // warp-uniform broadcast

    int j0 = l >> 3;                    // s row (0..3); second acc uses j0+4
    int u  = l & 7;                     // Ai column
    float acc0 = 0.0f, acc1 = 0.0f;
    float (*T)[34] = sT[w];

    for (int ch = 0; ch < nch; ch++) {
        int i = base + ch * 32 + l;
        if (i < end) {
            int src = __ldg(&g_csr[i]);
            float4 ps = __ldg(&g_node[4 * src]);
            float4 A0 = __ldg(&g_node[4 * src + 1]);
            float4 A1 = __ldg(&g_node[4 * src + 2]);
            float vx = pd.x - ps.x;
            float vy = pd.y - ps.y;
            float vz = pd.z - ps.z;
            if (cf) {   // exact: when cell==0 the shift term is identically 0
                int e = __ldg(&g_eid[i]);
                float shx = __ldg(shifts + 3 * e + 0);
                float shy = __ldg(shifts + 3 * e + 1);
                float shz = __ldg(shifts + 3 * e + 2);
                vx += shx * __ldg(cell + 0) + shy * __ldg(cell + 3) + shz * __ldg(cell + 6);
                vy += shx * __ldg(cell + 1) + shy * __ldg(cell + 4) + shz * __ldg(cell + 7);
                vz += shx * __ldg(cell + 2) + shy * __ldg(cell + 5) + shz * __ldg(cell + 8);
            }
            float len = sqrtf(vx * vx + vy * vy + vz * vz);
            float inv = 1.0f / fmaxf(len, 1e-8f);
            float nx = vx * inv, ny = vy * inv, nz = vz * inv;
            float s2 = nx * nx + ny * ny + nz * nz;   // 1 except degenerate edges

            float t = fminf(len * ((float)TBL_N / TBL_MAX), (float)TBL_N - 1.001f);
            int   i0 = (int)t;
            float fr = t - (float)i0;
            float4 Ta = __ldg(&g_table[i0]);       // 16KB table: L1-resident
            float4 Tb = __ldg(&g_table[i0 + 1]);
            float alpha = fmaf(fr, Tb.x - Ta.x, Ta.x);
            float gamma = fmaf(fr, Tb.y - Ta.y, Ta.y);
            float delta = fmaf(fr, Tb.z - Ta.z, Ta.z);
            float beta  = fmaf(fr, Tb.w - Ta.w, Ta.w) * s2;

            // transposed store: 16 conflict-free scalar STS (bank = (2k+l) mod 32)
            T[0][l]  = alpha;       T[1][l]  = beta;
            T[2][l]  = gamma * nx;  T[3][l]  = gamma * ny;
            T[4][l]  = gamma * nz;  T[5][l]  = delta * nx;
            T[6][l]  = delta * ny;  T[7][l]  = delta * nz;
            T[8][l]  = A0.x;  T[9][l]  = A0.y;  T[10][l] = A0.z;  T[11][l] = A0.w;
            T[12][l] = A1.x;  T[13][l] = A1.y;  T[14][l] = A1.z;  T[15][l] = A1.w;
        }
        __syncwarp();
        int m = deg - ch * 32;
        if (m > 32) m = 32;
        if (m == 32) {
#pragma unroll
            for (int c = 0; c < 32; c += 2) {       // LDS.64: 2 edges per iteration
                float2 a  = *(const float2*)&T[8 + u][c];
                float2 s0 = *(const float2*)&T[j0][c];
                float2 s1 = *(const float2*)&T[j0 + 4][c];
                acc0 = fmaf(s0.x, a.x, acc0);
                acc0 = fmaf(s0.y, a.y, acc0);
                acc1 = fmaf(s1.x, a.x, acc1);
                acc1 = fmaf(s1.y, a.y, acc1);
            }
        } else {
            int mp = m & ~1;
            for (int c = 0; c < mp; c += 2) {
                float2 a  = *(const float2*)&T[8 + u][c];
                float2 s0 = *(const float2*)&T[j0][c];
                float2 s1 = *(const float2*)&T[j0 + 4][c];
                acc0 = fmaf(s0.x, a.x, acc0);
                acc0 = fmaf(s0.y, a.y, acc0);
                acc1 = fmaf(s1.x, a.x, acc1);
                acc1 = fmaf(s1.y, a.y, acc1);
            }
            if (m & 1) {
                float a = T[8 + u][mp];
                acc0 = fmaf(T[j0][mp],     a, acc0);
                acc1 = fmaf(T[j0 + 4][mp], a, acc1);
            }
        }
        __syncwarp();
    }
    sAcc[w][l]      = acc0;           // entry (j0,  u)
    sAcc[w][l + 32] = acc1;           // entry (j0+4,u)
    __syncthreads();

    // ---- finalize: 1024 outputs (8 nodes x 128 cols), 4 per thread ----
    int col = tid & 127;
    float wa[8], wb[8];
    int ra, rb;
    if (col < 32) {
        int v = col;
#pragma unroll
        for (int uu = 0; uu < 8; uu++) {
            wa[uu] = sW[0 * 256 + uu * 32 + v];   // W0 * alpha row
            wb[uu] = sW[3 * 256 + uu * 32 + v];   // W3 * beta row
        }
        ra = 0; rb = 8;
    } else {
        int q = col - 32;
        int v = q / 3, o = q - 3 * v;
#pragma unroll
        for (int uu = 0; uu < 8; uu++) {
            wa[uu] = sW[1 * 256 + uu * 32 + v];   // W1 * gamma*n_o rows
            wb[uu] = sW[2 * 256 + uu * 32 + v];   // W2 * delta*n_o rows
        }
        ra = (2 + o) * 8; rb = (5 + o) * 8;
    }

    int w0 = tid >> 7;                // 0 or 1; this thread does nodes w0, w0+2, ...
#pragma unroll
    for (int k = 0; k < 4; k++) {
        int ws = w0 + k * 2;
        int nd = blockIdx.x * 8 + ws;
        if (nd >= N) break;
        float sum = 0.0f;
#pragma unroll
        for (int uu = 0; uu < 8; uu++) {
            sum = fmaf(wa[uu], sAcc[ws][ra + uu], sum);
            sum = fmaf(wb[uu], sAcc[ws][rb + uu], sum);
        }
        out[(size_t)nd * 128 + col] = sum * scale;
    }
}

// ---------------- launch ----------------
extern "C" void kernel_launch(void* const* d_in, const int* in_sizes, int n_in,
                              void* d_out, int out_size)
{
    const float* pos       = (const float*)d_in[0];
    const int*   A         = (const int*)  d_in[1];
    const int*   esrc      = (const int*)  d_in[3];
    const int*   edst      = (const int*)  d_in[4];
    const float* shifts    = (const float*)d_in[5];
    const float* cell      = (const float*)d_in[6];
    const float* emb_table = (const float*)d_in[7];
    const float* w1  = (const float*)d_in[8];
    const float* b1  = (const float*)d_in[9];
    const float* w2  = (const float*)d_in[10];
    const float* b2  = (const float*)d_in[11];
    const float* f1  = (const float*)d_in[12];
    const float* fb1 = (const float*)d_in[13];
    const float* f2  = (const float*)d_in[14];
    const float* fb2 = (const float*)d_in[15];
    const float* f3  = (const float*)d_in[16];
    const float* fb3 = (const float*)d_in[17];
    const float* tpw = (const float*)d_in[18];

    int N = in_sizes[1];
    int E = in_sizes[3];

    int nbTbl   = TBL_N / 256;
    int nbNode  = (N + 255) / 256;
    int nbCount = (E + 1023) / 1024;
    int nbScan  = (N + 255) / 256;

    prep_kernel<<<nbTbl + nbNode + nbCount, 256>>>(f1, fb1, f2, fb2, f3, fb3,
                                                   emb_table, A, w1, b1, w2, b2,
                                                   pos, cell, edst, N, E);
    scan_kernel<<<nbScan, 256>>>(N, E);
    permute_kernel<<<(E + 1023) / 1024, 256>>>(esrc, edst, E);
    gather_kernel<<<(N + 7) / 8, 256>>>(shifts, cell, tpw, (float*)d_out, N, (float)N / (float)E);
}

// round 14
// speedup vs baseline: 1.1582x; 1.0383x over previous
#include <cuda_runtime.h>
#include <cuda_fp16.h>
#include <math.h>

// ---------------- static scratch (no runtime allocation allowed) ----------------
#define TBL_N    1024
#define TBL_MAX  8.0f
#define NMAX     65536
#define EMAX     1700000

__device__ float4 g_table[TBL_N];            // (alpha,gamma,delta,beta') gate coeffs
__device__ float4 g_node[NMAX * 2];          // per node (32B): {pos.xyz,0},{Ai as 8 fp16}
__device__ int    g_cnt[NMAX];               // edge counts per dst (self-cleaning)
__device__ int    g_off[NMAX + 1];           // CSR offsets
__device__ unsigned long long g_aggflag[256];// lookback scan: (flag<<32)|aggregate
__device__ int    g_cellflag;                // 1 if cell has any nonzero entry
__device__ int    g_rank[EMAX];              // per-edge rank within dst segment
__device__ int    g_csr[EMAX];               // CSR: src node id per slot
__device__ int    g_eid[EMAX];               // CSR: edge id per slot (only if cellflag)

__device__ __forceinline__ float siluf(float x) { return x / (1.0f + expf(-x)); }

// ---------------- K1: fused prep (gate table | node pack+MLP | count+rank) ----------------
__global__ void __launch_bounds__(256) prep_kernel(
                            const float* __restrict__ f1, const float* __restrict__ fb1,
                            const float* __restrict__ f2, const float* __restrict__ fb2,
                            const float* __restrict__ f3, const float* __restrict__ fb3,
                            const float* __restrict__ emb_table, const int* __restrict__ A,
                            const float* __restrict__ w1, const float* __restrict__ b1,
                            const float* __restrict__ w2, const float* __restrict__ b2,
                            const float* __restrict__ pos, const float* __restrict__ cell,
                            const int* __restrict__ edst,
                            int N, int E)
{
    int tid = threadIdx.x;
    int bx = blockIdx.x;
    int nbTbl  = TBL_N / 256;
    int nbNode = (N + 255) / 256;

    if (bx < nbTbl) {
        // ---- gate table role (h1 fully register-resident: all indices static) ----
        if (bx == 0 && tid == 0) {
            int fl = 0;
            for (int i = 0; i < 9; i++) fl |= (cell[i] != 0.0f);
            g_cellflag = fl;
        }
        __shared__ float sf1[16 * 64];
        __shared__ float sf2[64 * 64];
        __shared__ float sf3[64 * 5];
        __shared__ float sb1[64], sb2[64], sb3[5];
        for (int i = tid; i < 16 * 64; i += 256) sf1[i] = f1[i];
        for (int i = tid; i < 64 * 64; i += 256) sf2[i] = f2[i];
        for (int i = tid; i < 64 * 5;  i += 256) sf3[i] = f3[i];
        if (tid < 64) { sb1[tid] = fb1[tid]; sb2[tid] = fb2[tid]; }
        if (tid < 5)  sb3[tid] = fb3[tid];
        __syncthreads();

        int idx = bx * 256 + tid;
        float x = (float)idx * (TBL_MAX / (float)TBL_N);
        float emb[16];
#pragma unroll
        for (int k = 0; k < 16; k++) {
            float c = (5.0f / 17.0f) * (float)(k + 1);
            float z = (x - c) * (17.0f / 5.0f);
            emb[k] = 3.57142857142857f * expf(-z * z);
        }
        float h1[64];
#pragma unroll
        for (int j = 0; j < 64; j++) {        // FULL unroll -> h1 writes static
            float a = sb1[j];
#pragma unroll
            for (int k = 0; k < 16; k++) a = fmaf(emb[k], sf1[k * 64 + j], a);
            h1[j] = siluf(a);
        }
        float g0 = sb3[0], g1 = sb3[1], g2 = sb3[2], g3 = sb3[3];
        for (int j = 0; j < 64; j++) {        // dynamic outer is fine
            float a = sb2[j];
#pragma unroll
            for (int k = 0; k < 64; k++)      // FULL unroll -> h1 reads static
                a = fmaf(h1[k], sf2[k * 64 + j], a);
            float h = siluf(a);
            g0 = fmaf(h, sf3[j * 5 + 0], g0);
            g1 = fmaf(h, sf3[j * 5 + 1], g1);
            g2 = fmaf(h, sf3[j * 5 + 2], g2);
            g3 = fmaf(h, sf3[j * 5 + 3], g3);
            // path (1,1,1): eps_mno n_m n_n == 0 -> dead, g4 never needed
        }
        const float IS8 = 0.3535533905932738f;
        const float IS3 = 0.5773502691896258f;
        float4 T;
        T.x = g0 * IS8;          // alpha
        T.y = g1 * IS8;          // gamma
        T.z = g2 * IS8;          // delta
        T.w = g3 * IS8 * IS3;    // beta (pre s2)
        g_table[idx] = T;
    } else if (bx < nbTbl + nbNode) {
        // ---- node MLP + pack role ----
        __shared__ float sw1[16 * 64];
        __shared__ float sw2[64 * 8];
        __shared__ float nb1[64], nb2[8];
        for (int i = tid; i < 16 * 64; i += 256) sw1[i] = w1[i];
        for (int i = tid; i < 64 * 8;  i += 256) sw2[i] = w2[i];
        if (tid < 64) nb1[tid] = b1[tid];
        if (tid < 8)  nb2[tid] = b2[tid];
        __syncthreads();

        int n = (bx - nbTbl) * 256 + tid;
        if (n >= N) return;
        int a = A[n];
        const float4* ep = (const float4*)(emb_table + (size_t)a * 16);
        float4 e0 = __ldg(ep + 0), e1 = __ldg(ep + 1), e2 = __ldg(ep + 2), e3 = __ldg(ep + 3);
        float e[16] = { e0.x, e0.y, e0.z, e0.w, e1.x, e1.y, e1.z, e1.w,
                        e2.x, e2.y, e2.z, e2.w, e3.x, e3.y, e3.z, e3.w };
        float acc[8];
#pragma unroll
        for (int u = 0; u < 8; u++) acc[u] = nb2[u];
        for (int j = 0; j < 64; j++) {
            float h = nb1[j];
#pragma unroll
            for (int k = 0; k < 16; k++) h = fmaf(e[k], sw1[k * 64 + j], h);
            h = siluf(h);
#pragma unroll
            for (int u = 0; u < 8; u++) acc[u] = fmaf(h, sw2[j * 8 + u], acc[u]);
        }
        g_node[2 * n + 0] = make_float4(pos[3 * n], pos[3 * n + 1], pos[3 * n + 2], 0.f);
        float4 hpack;
        __half2* hp = (__half2*)&hpack;
        hp[0] = __floats2half2_rn(acc[0], acc[1]);
        hp[1] = __floats2half2_rn(acc[2], acc[3]);
        hp[2] = __floats2half2_rn(acc[4], acc[5]);
        hp[3] = __floats2half2_rn(acc[6], acc[7]);
        g_node[2 * n + 1] = hpack;
    } else {
        // ---- count + rank role (independent of the other roles) ----
        int cb = bx - nbTbl - nbNode;
        if (cb == 0 && tid < 256) g_aggflag[tid] = 0ULL;
        int i = (cb * 256 + tid) * 4;
        if (i + 3 < E) {
            int4 d = *(const int4*)(edst + i);
            int4 r;
            r.x = atomicAdd(&g_cnt[d.x], 1);
            r.y = atomicAdd(&g_cnt[d.y], 1);
            r.z = atomicAdd(&g_cnt[d.z], 1);
            r.w = atomicAdd(&g_cnt[d.w], 1);
            *(int4*)(g_rank + i) = r;
        } else {
            for (int k = i; k < E; k++) g_rank[k] = atomicAdd(&g_cnt[edst[k]], 1);
        }
    }
}

// ---------------- K2: single-pass lookback scan -> offsets; self-clean counts ----------------
__global__ void scan_kernel(int N, int E)
{
    __shared__ int sm[256];
    __shared__ int sr[256];
    int t = threadIdx.x;
    int bx = blockIdx.x;
    int i = bx * 256 + t;
    int v = (i < N) ? g_cnt[i] : 0;
    if (i < N) g_cnt[i] = 0;          // reset for next graph replay

    sm[t] = v;
    __syncthreads();
#pragma unroll
    for (int d = 1; d < 256; d <<= 1) {
        int x = (t >= d) ? sm[t - d] : 0;
        __syncthreads();
        sm[t] += x;
        __syncthreads();
    }
    // publish aggregate (flag in high word, value in low word -> single 8B word, no fence)
    if (t == 0) atomicExch(&g_aggflag[bx], (1ULL << 32) | (unsigned int)sm[255]);

    // parallel lookback: thread t (< bx) polls block t's aggregate (plain volatile 8B load)
    int pre = 0;
    if (t < bx) {
        const volatile unsigned long long* p = (const volatile unsigned long long*)&g_aggflag[t];
        unsigned long long x;
        do { x = *p; } while (!(x >> 32));
        pre = (int)(unsigned int)x;
    }
    sr[t] = pre;
    __syncthreads();
#pragma unroll
    for (int d = 128; d > 0; d >>= 1) {
        if (t < d) sr[t] += sr[t + d];
        __syncthreads();
    }
    int prefix = sr[0];

    if (i < N) g_off[i] = prefix + sm[t] - v;   // exclusive
    if (bx == 0 && t == 0) g_off[N] = E;
}

// ---------------- K3: permute edges into CSR -- NO atomics (off + rank) ----------------
__global__ void permute_kernel(const int* __restrict__ esrc, const int* __restrict__ edst, int E)
{
    int cf = g_cellflag;
    int i = (blockIdx.x * blockDim.x + threadIdx.x) * 4;
    if (i + 3 < E) {
        int4 s4 = *(const int4*)(esrc + i);
        int4 d4 = *(const int4*)(edst + i);
        int4 r4 = *(const int4*)(g_rank + i);
        int sl;
        sl = __ldg(&g_off[d4.x]) + r4.x; g_csr[sl] = s4.x; if (cf) g_eid[sl] = i;
        sl = __ldg(&g_off[d4.y]) + r4.y; g_csr[sl] = s4.y; if (cf) g_eid[sl] = i + 1;
        sl = __ldg(&g_off[d4.z]) + r4.z; g_csr[sl] = s4.z; if (cf) g_eid[sl] = i + 2;
        sl = __ldg(&g_off[d4.w]) + r4.w; g_csr[sl] = s4.w; if (cf) g_eid[sl] = i + 3;
    } else {
        for (int k = i; k < E; k++) {
            int sl = __ldg(&g_off[edst[k]]) + g_rank[k];
            g_csr[sl] = esrc[k];
            if (cf) g_eid[sl] = k;
        }
    }
}

// ---------------- K4: warp-per-node gather + fused finalize (32B node records) ----------------
__global__ void __launch_bounds__(256) gather_kernel(
    const float* __restrict__ shifts, const float* __restrict__ cell,
    const float* __restrict__ tpw, float* __restrict__ out, int N, float scale)
{
    __shared__ float sT[8][16][34];     // per-warp transposed staging (stride 34)
    __shared__ float sAcc[8][64];       // per-node sufficient statistics
    __shared__ float sW[1024];          // tpw[4 paths][8][32]

    int tid = threadIdx.x;
    int w   = tid >> 5;                 // warp / node slot
    int l   = tid & 31;                 // lane
    for (int i = tid; i < 1024; i += 256) sW[i] = __ldg(tpw + i);

    int node = blockIdx.x * 8 + w;
    int base = 0, end = 0;
    if (node < N) { base = g_off[node]; end = g_off[node + 1]; }
    int deg = end - base;
    int nch = (deg + 31) >> 5;
    int cf  = g_cellflag;

    float4 pd = make_float4(0.f, 0.f, 0.f, 0.f);
    if (node < N) pd = __ldg(&g_node[2 * node]);   // warp-uniform broadcast

    int j0 = l >> 3;                    // s row (0..3); second acc uses j0+4
    int u  = l & 7;                     // Ai column
    float acc0 = 0.0f, acc1 = 0.0f;
    float (*T)[34] = sT[w];

    for (int ch = 0; ch < nch; ch++) {
        int i = base + ch * 32 + l;
        if (i < end) {
            int src = __ldg(&g_csr[i]);
            float4 ps = __ldg(&g_node[2 * src]);         // pos
            float4 hA = __ldg(&g_node[2 * src + 1]);     // Ai fp16x8
            const __half2* hp = (const __half2*)&hA;
            float2 a01 = __half22float2(hp[0]);
            float2 a23 = __half22float2(hp[1]);
            float2 a45 = __half22float2(hp[2]);
            float2 a67 = __half22float2(hp[3]);

            float vx = pd.x - ps.x;
            float vy = pd.y - ps.y;
            float vz = pd.z - ps.z;
            if (cf) {   // exact: when cell==0 the shift term is identically 0
                int e = __ldg(&g_eid[i]);
                float shx = __ldg(shifts + 3 * e + 0);
                float shy = __ldg(shifts + 3 * e + 1);
                float shz = __ldg(shifts + 3 * e + 2);
                vx += shx * __ldg(cell + 0) + shy * __ldg(cell + 3) + shz * __ldg(cell + 6);
                vy += shx * __ldg(cell + 1) + shy * __ldg(cell + 4) + shz * __ldg(cell + 7);
                vz += shx * __ldg(cell + 2) + shy * __ldg(cell + 5) + shz * __ldg(cell + 8);
            }
            float len = sqrtf(vx * vx + vy * vy + vz * vz);
            float inv = 1.0f / fmaxf(len, 1e-8f);
            float nx = vx * inv, ny = vy * inv, nz = vz * inv;
            float s2 = nx * nx + ny * ny + nz * nz;   // 1 except degenerate edges

            float t = fminf(len * ((float)TBL_N / TBL_MAX), (float)TBL_N - 1.001f);
            int   i0 = (int)t;
            float fr = t - (float)i0;
            float4 Ta = __ldg(&g_table[i0]);       // 16KB table: L1-resident
            float4 Tb = __ldg(&g_table[i0 + 1]);
            float alpha = fmaf(fr, Tb.x - Ta.x, Ta.x);
            float gamma = fmaf(fr, Tb.y - Ta.y, Ta.y);
            float delta = fmaf(fr, Tb.z - Ta.z, Ta.z);
            float beta  = fmaf(fr, Tb.w - Ta.w, Ta.w) * s2;

            // transposed store: 16 conflict-free scalar STS (bank = (2k+l) mod 32)
            T[0][l]  = alpha;       T[1][l]  = beta;
            T[2][l]  = gamma * nx;  T[3][l]  = gamma * ny;
            T[4][l]  = gamma * nz;  T[5][l]  = delta * nx;
            T[6][l]  = delta * ny;  T[7][l]  = delta * nz;
            T[8][l]  = a01.x;  T[9][l]  = a01.y;  T[10][l] = a23.x;  T[11][l] = a23.y;
            T[12][l] = a45.x;  T[13][l] = a45.y;  T[14][l] = a67.x;  T[15][l] = a67.y;
        }
        __syncwarp();
        int m = deg - ch * 32;
        if (m > 32) m = 32;
        if (m == 32) {
#pragma unroll
            for (int c = 0; c < 32; c += 2) {       // LDS.64: 2 edges per iteration
                float2 a  = *(const float2*)&T[8 + u][c];
                float2 s0 = *(const float2*)&T[j0][c];
                float2 s1 = *(const float2*)&T[j0 + 4][c];
                acc0 = fmaf(s0.x, a.x, acc0);
                acc0 = fmaf(s0.y, a.y, acc0);
                acc1 = fmaf(s1.x, a.x, acc1);
                acc1 = fmaf(s1.y, a.y, acc1);
            }
        } else {
            int mp = m & ~1;
            for (int c = 0; c < mp; c += 2) {
                float2 a  = *(const float2*)&T[8 + u][c];
                float2 s0 = *(const float2*)&T[j0][c];
                float2 s1 = *(const float2*)&T[j0 + 4][c];
                acc0 = fmaf(s0.x, a.x, acc0);
                acc0 = fmaf(s0.y, a.y, acc0);
                acc1 = fmaf(s1.x, a.x, acc1);
                acc1 = fmaf(s1.y, a.y, acc1);
            }
            if (m & 1) {
                float a = T[8 + u][mp];
                acc0 = fmaf(T[j0][mp],     a, acc0);
                acc1 = fmaf(T[j0 + 4][mp], a, acc1);
            }
        }
        __syncwarp();
    }
    sAcc[w][l]      = acc0;           // entry (j0,  u)
    sAcc[w][l + 32] = acc1;           // entry (j0+4,u)
    __syncthreads();

    // ---- finalize: 1024 outputs (8 nodes x 128 cols), 4 per thread ----
    int col = tid & 127;
    float wa[8], wb[8];
    int ra, rb;
    if (col < 32) {
        int v = col;
#pragma unroll
        for (int uu = 0; uu < 8; uu++) {
            wa[uu] = sW[0 * 256 + uu * 32 + v];   // W0 * alpha row
            wb[uu] = sW[3 * 256 + uu * 32 + v];   // W3 * beta row
        }
        ra = 0; rb = 8;
    } else {
        int q = col - 32;
        int v = q / 3, o = q - 3 * v;
#pragma unroll
        for (int uu = 0; uu < 8; uu++) {
            wa[uu] = sW[1 * 256 + uu * 32 + v];   // W1 * gamma*n_o rows
            wb[uu] = sW[2 * 256 + uu * 32 + v];   // W2 * delta*n_o rows
        }
        ra = (2 + o) * 8; rb = (5 + o) * 8;
    }

    int w0 = tid >> 7;                // 0 or 1; this thread does nodes w0, w0+2, ...
#pragma unroll
    for (int k = 0; k < 4; k++) {
        int ws = w0 + k * 2;
        int nd = blockIdx.x * 8 + ws;
        if (nd >= N) break;
        float sum = 0.0f;
#pragma unroll
        for (int uu = 0; uu < 8; uu++) {
            sum = fmaf(wa[uu], sAcc[ws][ra + uu], sum);
            sum = fmaf(wb[uu], sAcc[ws][rb + uu], sum);
        }
        out[(size_t)nd * 128 + col] = sum * scale;
    }
}

// ---------------- launch ----------------
extern "C" void kernel_launch(void* const* d_in, const int* in_sizes, int n_in,
                              void* d_out, int out_size)
{
    const float* pos       = (const float*)d_in[0];
    const int*   A         = (const int*)  d_in[1];
    const int*   esrc      = (const int*)  d_in[3];
    const int*   edst      = (const int*)  d_in[4];
    const float* shifts    = (const float*)d_in[5];
    const float* cell      = (const float*)d_in[6];
    const float* emb_table = (const float*)d_in[7];
    const float* w1  = (const float*)d_in[8];
    const float* b1  = (const float*)d_in[9];
    const float* w2  = (const float*)d_in[10];
    const float* b2  = (const float*)d_in[11];
    const float* f1  = (const float*)d_in[12];
    const float* fb1 = (const float*)d_in[13];
    const float* f2  = (const float*)d_in[14];
    const float* fb2 = (const float*)d_in[15];
    const float* f3  = (const float*)d_in[16];
    const float* fb3 = (const float*)d_in[17];
    const float* tpw = (const float*)d_in[18];

    int N = in_sizes[1];
    int E = in_sizes[3];

    int nbTbl   = TBL_N / 256;
    int nbNode  = (N + 255) / 256;
    int nbCount = (E + 1023) / 1024;
    int nbScan  = (N + 255) / 256;

    prep_kernel<<<nbTbl + nbNode + nbCount, 256>>>(f1, fb1, f2, fb2, f3, fb3,
                                                   emb_table, A, w1, b1, w2, b2,
                                                   pos, cell, edst, N, E);
    scan_kernel<<<nbScan, 256>>>(N, E);
    permute_kernel<<<(E + 1023) / 1024, 256>>>(esrc, edst, E);
    gather_kernel<<<(N + 7) / 8, 256>>>(shifts, cell, tpw, (float*)d_out, N, (float)N / (float)E);
}